// round 1
// baseline (speedup 1.0000x reference)
#include <cuda_runtime.h>
#include <math.h>

#define B_  2
#define S_  2048
#define D_  1024
#define H_  16
#define DK_ 64
#define N_  (B_*S_)

// Scratch (device globals — no allocation allowed)
__device__ float g_Qh[N_*D_];   // [B,H,S,DK]
__device__ float g_Kh[N_*D_];
__device__ float g_Vh[N_*D_];
__device__ float g_ctx[N_*D_];  // [B,S,D]

// ---------------------------------------------------------------------------
// SGEMM: Y = X @ W + bias.  X:[4096,1024] row-major, W:[1024,1024] row-major.
// SPLIT=true stores Y in head-split [B,H,S,DK] layout.
// 128x128 tile, BK=8, 256 threads, 8x8 per-thread microtile.
// ---------------------------------------------------------------------------
template<bool SPLIT>
__global__ __launch_bounds__(256) void sgemm_bias_kernel(
    const float* __restrict__ X, const float* __restrict__ W,
    const float* __restrict__ bias, float* __restrict__ Y)
{
    __shared__ float As[8][132];   // transposed A tile: As[k][m]
    __shared__ float Bs[8][128];   // B tile: Bs[k][n]

    const int tid = threadIdx.x;
    const int tx = tid & 15, ty = tid >> 4;
    const int rowBase = blockIdx.y * 128;
    const int colBase = blockIdx.x * 128;

    float acc[8][8];
    #pragma unroll
    for (int i = 0; i < 8; i++)
        #pragma unroll
        for (int j = 0; j < 8; j++) acc[i][j] = 0.f;

    const int ar = tid >> 1, akq = (tid & 1) * 4;     // A load: row, k-quad
    const int br = tid >> 5, bc = (tid & 31) * 4;     // B load: k-row, col-quad
    const float* Xp = X + (rowBase + ar) * D_ + akq;
    const float* Wp = W + br * D_ + colBase + bc;

    for (int kt = 0; kt < D_; kt += 8) {
        float4 a4 = *(const float4*)(Xp + kt);
        As[akq+0][ar] = a4.x;
        As[akq+1][ar] = a4.y;
        As[akq+2][ar] = a4.z;
        As[akq+3][ar] = a4.w;
        *(float4*)&Bs[br][bc] = *(const float4*)(Wp + (size_t)kt * D_);
        __syncthreads();

        #pragma unroll
        for (int k = 0; k < 8; k++) {
            float a[8], b[8];
            *(float4*)&a[0] = *(const float4*)&As[k][ty*8];
            *(float4*)&a[4] = *(const float4*)&As[k][ty*8+4];
            *(float4*)&b[0] = *(const float4*)&Bs[k][tx*8];
            *(float4*)&b[4] = *(const float4*)&Bs[k][tx*8+4];
            #pragma unroll
            for (int i = 0; i < 8; i++)
                #pragma unroll
                for (int j = 0; j < 8; j++)
                    acc[i][j] += a[i]*b[j];
        }
        __syncthreads();
    }

    #pragma unroll
    for (int i = 0; i < 8; i++) {
        const int r = rowBase + ty*8 + i;
        #pragma unroll
        for (int jj = 0; jj < 8; jj += 4) {
            const int c = colBase + tx*8 + jj;
            const float4 bb = *(const float4*)&bias[c];
            float4 v;
            v.x = acc[i][jj+0] + bb.x;
            v.y = acc[i][jj+1] + bb.y;
            v.z = acc[i][jj+2] + bb.z;
            v.w = acc[i][jj+3] + bb.w;
            if (SPLIT) {
                const int b  = r >> 11;          // r / S_
                const int s  = r & (S_-1);
                const int h  = c >> 6;           // c / DK_
                const int dk = c & (DK_-1);
                *(float4*)&Y[(((b*H_ + h)*S_) + s)*DK_ + dk] = v;
            } else {
                *(float4*)&Y[(size_t)r*D_ + c] = v;
            }
        }
    }
}

// ---------------------------------------------------------------------------
// Causal flash attention, fp32. One CTA per (q-tile of 64 rows, head).
// Br=Bc=64, 256 threads as 16x16, 4x4 microtiles, online softmax.
// smem: Qs^T [64][65], Ks^T [64][65] (reused as P^T), Vs [64][64] = 49664 B.
// ---------------------------------------------------------------------------
__global__ __launch_bounds__(256) void attn_kernel(float* __restrict__ ctx)
{
    extern __shared__ float sm[];
    float* Qs = sm;             // Qs[d*65 + r]
    float* Ks = sm + 64*65;     // Ks[d*65 + c]; later P^T[c*65 + r]
    float* Vs = sm + 2*64*65;   // Vs[c*64 + d]

    const int tid = threadIdx.x;
    const int tx = tid & 15, ty = tid >> 4;
    const int qt = blockIdx.x, bh = blockIdx.y;

    const float* Qg = g_Qh + (size_t)bh * (S_*DK_) + qt * 64 * DK_;
    const float* Kg = g_Kh + (size_t)bh * (S_*DK_);
    const float* Vg = g_Vh + (size_t)bh * (S_*DK_);

    // Load Q tile transposed (once)
    #pragma unroll
    for (int i = 0; i < 4; i++) {
        const int idx = tid + 256*i;          // 0..1023 float4 slots
        const int r = idx >> 4, cq = (idx & 15) * 4;
        const float4 v = *(const float4*)&Qg[r*DK_ + cq];
        Qs[(cq+0)*65 + r] = v.x;
        Qs[(cq+1)*65 + r] = v.y;
        Qs[(cq+2)*65 + r] = v.z;
        Qs[(cq+3)*65 + r] = v.w;
    }

    float m[4], l[4], o[4][4];
    #pragma unroll
    for (int i = 0; i < 4; i++) {
        m[i] = -1e30f; l[i] = 0.f;
        #pragma unroll
        for (int j = 0; j < 4; j++) o[i][j] = 0.f;
    }

    for (int kt = 0; kt <= qt; kt++) {
        __syncthreads();   // prev iter done with Ks/Vs (and orders Q store, 1st iter)
        // Load K (transposed) and V (row-major) tiles
        #pragma unroll
        for (int i = 0; i < 4; i++) {
            const int idx = tid + 256*i;
            const int r = idx >> 4, cq = (idx & 15) * 4;
            const float4 kv = *(const float4*)&Kg[(kt*64 + r)*DK_ + cq];
            Ks[(cq+0)*65 + r] = kv.x;
            Ks[(cq+1)*65 + r] = kv.y;
            Ks[(cq+2)*65 + r] = kv.z;
            Ks[(cq+3)*65 + r] = kv.w;
            const float4 vv = *(const float4*)&Vg[(kt*64 + r)*DK_ + cq];
            *(float4*)&Vs[r*64 + cq] = vv;
        }
        __syncthreads();

        // S = Q K^T
        float s[4][4];
        #pragma unroll
        for (int i = 0; i < 4; i++)
            #pragma unroll
            for (int j = 0; j < 4; j++) s[i][j] = 0.f;

        #pragma unroll 16
        for (int d = 0; d < 64; d++) {
            float qv[4], kv[4];
            #pragma unroll
            for (int i = 0; i < 4; i++) qv[i] = Qs[d*65 + ty*4 + i];
            #pragma unroll
            for (int j = 0; j < 4; j++) kv[j] = Ks[d*65 + tx*4 + j];
            #pragma unroll
            for (int i = 0; i < 4; i++)
                #pragma unroll
                for (int j = 0; j < 4; j++)
                    s[i][j] += qv[i]*kv[j];
        }

        // scale + causal mask on the diagonal tile
        #pragma unroll
        for (int i = 0; i < 4; i++)
            #pragma unroll
            for (int j = 0; j < 4; j++) {
                float val = s[i][j] * 0.125f;
                if (kt == qt && (tx*4 + j) > (ty*4 + i)) val = -1e30f;
                s[i][j] = val;
            }

        // online softmax (row stats across 16 tx lanes via shfl)
        float p[4][4];
        #pragma unroll
        for (int i = 0; i < 4; i++) {
            float rm = fmaxf(fmaxf(s[i][0], s[i][1]), fmaxf(s[i][2], s[i][3]));
            rm = fmaxf(rm, __shfl_xor_sync(0xffffffffu, rm, 1));
            rm = fmaxf(rm, __shfl_xor_sync(0xffffffffu, rm, 2));
            rm = fmaxf(rm, __shfl_xor_sync(0xffffffffu, rm, 4));
            rm = fmaxf(rm, __shfl_xor_sync(0xffffffffu, rm, 8));
            const float mn = fmaxf(m[i], rm);
            const float alpha = __expf(m[i] - mn);
            m[i] = mn;
            float rs = 0.f;
            #pragma unroll
            for (int j = 0; j < 4; j++) {
                p[i][j] = __expf(s[i][j] - mn);
                rs += p[i][j];
            }
            rs += __shfl_xor_sync(0xffffffffu, rs, 1);
            rs += __shfl_xor_sync(0xffffffffu, rs, 2);
            rs += __shfl_xor_sync(0xffffffffu, rs, 4);
            rs += __shfl_xor_sync(0xffffffffu, rs, 8);
            l[i] = l[i]*alpha + rs;
            #pragma unroll
            for (int j = 0; j < 4; j++) o[i][j] *= alpha;
        }

        __syncthreads();   // everyone done reading Ks before overwrite with P^T
        #pragma unroll
        for (int i = 0; i < 4; i++)
            #pragma unroll
            for (int j = 0; j < 4; j++)
                Ks[(tx*4 + j)*65 + ty*4 + i] = p[i][j];
        __syncthreads();

        // O += P V
        #pragma unroll 16
        for (int c = 0; c < 64; c++) {
            float pv[4], vv[4];
            #pragma unroll
            for (int i = 0; i < 4; i++) pv[i] = Ks[c*65 + ty*4 + i];
            #pragma unroll
            for (int j = 0; j < 4; j++) vv[j] = Vs[c*64 + tx*4 + j];
            #pragma unroll
            for (int i = 0; i < 4; i++)
                #pragma unroll
                for (int j = 0; j < 4; j++)
                    o[i][j] += pv[i]*vv[j];
        }
    }

    // epilogue: normalize and store to ctx in [B,S,D] layout
    const int b = bh >> 4, h = bh & 15;
    #pragma unroll
    for (int i = 0; i < 4; i++) {
        const int r = qt*64 + ty*4 + i;
        const float inv = 1.0f / l[i];
        float4 v;
        v.x = o[i][0]*inv; v.y = o[i][1]*inv; v.z = o[i][2]*inv; v.w = o[i][3]*inv;
        *(float4*)&ctx[((size_t)b*S_ + r)*D_ + h*DK_ + tx*4] = v;
    }
}

// ---------------------------------------------------------------------------
extern "C" void kernel_launch(void* const* d_in, const int* in_sizes, int n_in,
                              void* d_out, int out_size)
{
    const float* q   = (const float*)d_in[0];
    const float* k   = (const float*)d_in[1];
    const float* v   = (const float*)d_in[2];
    // d_in[3] = mask (causal tril, applied analytically)
    const float* w_q = (const float*)d_in[4];
    const float* b_q = (const float*)d_in[5];
    const float* w_k = (const float*)d_in[6];
    const float* b_k = (const float*)d_in[7];
    const float* w_v = (const float*)d_in[8];
    const float* b_v = (const float*)d_in[9];
    const float* w_o = (const float*)d_in[10];
    const float* b_o = (const float*)d_in[11];
    float* out = (float*)d_out;

    float *Qh, *Kh, *Vh, *ctx;
    cudaGetSymbolAddress((void**)&Qh,  g_Qh);
    cudaGetSymbolAddress((void**)&Kh,  g_Kh);
    cudaGetSymbolAddress((void**)&Vh,  g_Vh);
    cudaGetSymbolAddress((void**)&ctx, g_ctx);

    const int attn_smem = (2*64*65 + 64*64) * sizeof(float);   // 49664 B
    cudaFuncSetAttribute(attn_kernel,
                         cudaFuncAttributeMaxDynamicSharedMemorySize, attn_smem);

    const dim3 gemm_grid(D_/128, N_/128);   // (8, 32)
    sgemm_bias_kernel<true ><<<gemm_grid, 256>>>(q, w_q, b_q, Qh);
    sgemm_bias_kernel<true ><<<gemm_grid, 256>>>(k, w_k, b_k, Kh);
    sgemm_bias_kernel<true ><<<gemm_grid, 256>>>(v, w_v, b_v, Vh);

    attn_kernel<<<dim3(S_/64, B_*H_), 256, attn_smem>>>(ctx);

    sgemm_bias_kernel<false><<<gemm_grid, 256>>>(ctx, w_o, b_o, out);
}

// round 5
// speedup vs baseline: 1.4744x; 1.4744x over previous
#include <cuda_runtime.h>
#include <cstdint>
#include <math.h>

#define B_  2
#define S_  2048
#define D_  1024
#define H_  16
#define DK_ 64
#define N_  (B_*S_)

// Scratch (device globals — no allocation allowed)
__device__ float g_Qh[N_*D_];   // [B,H,S,DK]
__device__ float g_Kh[N_*D_];
__device__ float g_Vh[N_*D_];
__device__ float g_ctx[N_*D_];  // [B,S,D]

// ============================ helpers ======================================
__device__ __forceinline__ uint32_t f2tf32(float x) {   // round-to-nearest tf32
    uint32_t r;
    asm("cvt.rna.tf32.f32 %0, %1;" : "=r"(r) : "f"(x));
    return r;
}

__device__ __forceinline__ void mma_tf32(float c[4],
                                         uint32_t a0, uint32_t a1, uint32_t a2, uint32_t a3,
                                         uint32_t b0, uint32_t b1) {
    asm volatile(
        "mma.sync.aligned.m16n8k8.row.col.f32.tf32.tf32.f32 "
        "{%0,%1,%2,%3}, {%4,%5,%6,%7}, {%8,%9}, {%0,%1,%2,%3};"
        : "+f"(c[0]), "+f"(c[1]), "+f"(c[2]), "+f"(c[3])
        : "r"(a0), "r"(a1), "r"(a2), "r"(a3), "r"(b0), "r"(b1));
}

// ===========================================================================
// tf32 tensor-core GEMM: Y = X @ W + bias.
// X:[4096,1024] row-major, W:[1024,1024] row-major.
// CTA 128x128, K-chunk 32, 8 warps (2m x 4n), warp tile 64x32.
// smem: As[m][k] stride 36 (conflict-free frags + vec stores),
//       Bs[k][n] stride 136 (conflict-free frags + vec stores). Double-buffered.
// ===========================================================================
#define AS_STRIDE 36
#define BS_STRIDE 136
#define AS_FLOATS (128 * AS_STRIDE)     // 4608
#define BS_FLOATS (32 * BS_STRIDE)      // 4352
#define GEMM_SMEM ((2*AS_FLOATS + 2*BS_FLOATS) * 4)   // 71680 B

template<bool SPLIT>
__global__ __launch_bounds__(256, 2)
void gemm_mma_kernel(const float* __restrict__ X, const float* __restrict__ W,
                     const float* __restrict__ bias, float* __restrict__ Y)
{
    extern __shared__ float sm[];
    float* Asb[2] = { sm, sm + AS_FLOATS };
    float* Bsb[2] = { sm + 2*AS_FLOATS, sm + 2*AS_FLOATS + BS_FLOATS };

    const int tid  = threadIdx.x;
    const int wid  = tid >> 5, lane = tid & 31;
    const int g    = lane >> 2, t4 = lane & 3;
    const int wm   = wid >> 2, wn = wid & 3;
    const int rowBase = blockIdx.y * 128;
    const int colBase = blockIdx.x * 128;

    float acc[4][4][4];
    #pragma unroll
    for (int mt = 0; mt < 4; mt++)
        #pragma unroll
        for (int nt = 0; nt < 4; nt++)
            #pragma unroll
            for (int r = 0; r < 4; r++) acc[mt][nt][r] = 0.f;

    // ---- prologue: load chunk 0 directly into buffer 0 ----
    #pragma unroll
    for (int j = 0; j < 4; j++) {
        const int slot = tid + 256 * j;
        const int row = slot >> 3, f4 = slot & 7;
        const float4 a = *(const float4*)&X[(size_t)(rowBase + row) * D_ + f4 * 4];
        uint4 ta;
        ta.x = f2tf32(a.x); ta.y = f2tf32(a.y); ta.z = f2tf32(a.z); ta.w = f2tf32(a.w);
        *(uint4*)&Asb[0][row * AS_STRIDE + f4 * 4] = ta;
        const int kr = slot >> 5, nq = slot & 31;
        const float4 b = *(const float4*)&W[(size_t)kr * D_ + colBase + nq * 4];
        uint4 tb;
        tb.x = f2tf32(b.x); tb.y = f2tf32(b.y); tb.z = f2tf32(b.z); tb.w = f2tf32(b.w);
        *(uint4*)&Bsb[0][kr * BS_STRIDE + nq * 4] = tb;
    }

    int buf = 0;
    for (int ch = 0; ch < 32; ch++) {
        __syncthreads();

        // prefetch next chunk into registers
        float4 ar[4], br[4];
        const bool has_next = (ch + 1 < 32);
        if (has_next) {
            #pragma unroll
            for (int j = 0; j < 4; j++) {
                const int slot = tid + 256 * j;
                const int row = slot >> 3, f4 = slot & 7;
                ar[j] = *(const float4*)&X[(size_t)(rowBase + row) * D_ + (ch+1)*32 + f4 * 4];
                const int kr = slot >> 5, nq = slot & 31;
                br[j] = *(const float4*)&W[(size_t)((ch+1)*32 + kr) * D_ + colBase + nq * 4];
            }
        }

        // compute on current buffer
        const float* A = Asb[buf];
        const float* Bv = Bsb[buf];
        #pragma unroll
        for (int ks = 0; ks < 4; ks++) {
            const int k0 = ks * 8;
            uint32_t a[4][4];
            #pragma unroll
            for (int mt = 0; mt < 4; mt++) {
                const int m0 = wm * 64 + mt * 16;
                a[mt][0] = __float_as_uint(A[(m0 + g    ) * AS_STRIDE + k0 + t4    ]);
                a[mt][1] = __float_as_uint(A[(m0 + g + 8) * AS_STRIDE + k0 + t4    ]);
                a[mt][2] = __float_as_uint(A[(m0 + g    ) * AS_STRIDE + k0 + t4 + 4]);
                a[mt][3] = __float_as_uint(A[(m0 + g + 8) * AS_STRIDE + k0 + t4 + 4]);
            }
            #pragma unroll
            for (int nt = 0; nt < 4; nt++) {
                const int n0 = wn * 32 + nt * 8;
                const uint32_t b0 = __float_as_uint(Bv[(k0 + t4    ) * BS_STRIDE + n0 + g]);
                const uint32_t b1 = __float_as_uint(Bv[(k0 + t4 + 4) * BS_STRIDE + n0 + g]);
                #pragma unroll
                for (int mt = 0; mt < 4; mt++)
                    mma_tf32(acc[mt][nt], a[mt][0], a[mt][1], a[mt][2], a[mt][3], b0, b1);
            }
        }

        // store prefetched chunk into the other buffer
        if (has_next) {
            float* An = Asb[buf ^ 1];
            float* Bn = Bsb[buf ^ 1];
            #pragma unroll
            for (int j = 0; j < 4; j++) {
                const int slot = tid + 256 * j;
                const int row = slot >> 3, f4 = slot & 7;
                uint4 ta;
                ta.x = f2tf32(ar[j].x); ta.y = f2tf32(ar[j].y);
                ta.z = f2tf32(ar[j].z); ta.w = f2tf32(ar[j].w);
                *(uint4*)&An[row * AS_STRIDE + f4 * 4] = ta;
                const int kr = slot >> 5, nq = slot & 31;
                uint4 tb;
                tb.x = f2tf32(br[j].x); tb.y = f2tf32(br[j].y);
                tb.z = f2tf32(br[j].z); tb.w = f2tf32(br[j].w);
                *(uint4*)&Bn[kr * BS_STRIDE + nq * 4] = tb;
            }
        }
        buf ^= 1;
    }

    // ---- epilogue: bias + store ----
    #pragma unroll
    for (int mt = 0; mt < 4; mt++) {
        const int r0 = rowBase + wm * 64 + mt * 16 + g;
        #pragma unroll
        for (int nt = 0; nt < 4; nt++) {
            const int cb = colBase + wn * 32 + nt * 8 + t4 * 2;
            const float2 bb = *(const float2*)&bias[cb];
            float2 v0, v1;
            v0.x = acc[mt][nt][0] + bb.x; v0.y = acc[mt][nt][1] + bb.y;
            v1.x = acc[mt][nt][2] + bb.x; v1.y = acc[mt][nt][3] + bb.y;
            if (SPLIT) {
                const int h = cb >> 6, dk = cb & (DK_-1);
                const int b0i = r0 >> 11, s0 = r0 & (S_-1);
                *(float2*)&Y[(((b0i*H_ + h)*S_) + s0)*DK_ + dk] = v0;
                const int r1 = r0 + 8;
                const int b1i = r1 >> 11, s1 = r1 & (S_-1);
                *(float2*)&Y[(((b1i*H_ + h)*S_) + s1)*DK_ + dk] = v1;
            } else {
                *(float2*)&Y[(size_t)r0 * D_ + cb] = v0;
                *(float2*)&Y[(size_t)(r0 + 8) * D_ + cb] = v1;
            }
        }
    }
}

// ---------------------------------------------------------------------------
// Causal flash attention, fp32 (unchanged).
// ---------------------------------------------------------------------------
__global__ __launch_bounds__(256) void attn_kernel(float* __restrict__ ctx)
{
    extern __shared__ float smf[];
    float* Qs = smf;             // Qs[d*65 + r]
    float* Ks = smf + 64*65;     // Ks[d*65 + c]; later P^T[c*65 + r]
    float* Vs = smf + 2*64*65;   // Vs[c*64 + d]

    const int tid = threadIdx.x;
    const int tx = tid & 15, ty = tid >> 4;
    const int qt = blockIdx.x, bh = blockIdx.y;

    const float* Qg = g_Qh + (size_t)bh * (S_*DK_) + qt * 64 * DK_;
    const float* Kg = g_Kh + (size_t)bh * (S_*DK_);
    const float* Vg = g_Vh + (size_t)bh * (S_*DK_);

    #pragma unroll
    for (int i = 0; i < 4; i++) {
        const int idx = tid + 256*i;
        const int r = idx >> 4, cq = (idx & 15) * 4;
        const float4 v = *(const float4*)&Qg[r*DK_ + cq];
        Qs[(cq+0)*65 + r] = v.x;
        Qs[(cq+1)*65 + r] = v.y;
        Qs[(cq+2)*65 + r] = v.z;
        Qs[(cq+3)*65 + r] = v.w;
    }

    float m[4], l[4], o[4][4];
    #pragma unroll
    for (int i = 0; i < 4; i++) {
        m[i] = -1e30f; l[i] = 0.f;
        #pragma unroll
        for (int j = 0; j < 4; j++) o[i][j] = 0.f;
    }

    for (int kt = 0; kt <= qt; kt++) {
        __syncthreads();
        #pragma unroll
        for (int i = 0; i < 4; i++) {
            const int idx = tid + 256*i;
            const int r = idx >> 4, cq = (idx & 15) * 4;
            const float4 kv = *(const float4*)&Kg[(kt*64 + r)*DK_ + cq];
            Ks[(cq+0)*65 + r] = kv.x;
            Ks[(cq+1)*65 + r] = kv.y;
            Ks[(cq+2)*65 + r] = kv.z;
            Ks[(cq+3)*65 + r] = kv.w;
            const float4 vv = *(const float4*)&Vg[(kt*64 + r)*DK_ + cq];
            *(float4*)&Vs[r*64 + cq] = vv;
        }
        __syncthreads();

        float s[4][4];
        #pragma unroll
        for (int i = 0; i < 4; i++)
            #pragma unroll
            for (int j = 0; j < 4; j++) s[i][j] = 0.f;

        #pragma unroll 16
        for (int d = 0; d < 64; d++) {
            float qv[4], kv[4];
            #pragma unroll
            for (int i = 0; i < 4; i++) qv[i] = Qs[d*65 + ty*4 + i];
            #pragma unroll
            for (int j = 0; j < 4; j++) kv[j] = Ks[d*65 + tx*4 + j];
            #pragma unroll
            for (int i = 0; i < 4; i++)
                #pragma unroll
                for (int j = 0; j < 4; j++)
                    s[i][j] += qv[i]*kv[j];
        }

        #pragma unroll
        for (int i = 0; i < 4; i++)
            #pragma unroll
            for (int j = 0; j < 4; j++) {
                float val = s[i][j] * 0.125f;
                if (kt == qt && (tx*4 + j) > (ty*4 + i)) val = -1e30f;
                s[i][j] = val;
            }

        float p[4][4];
        #pragma unroll
        for (int i = 0; i < 4; i++) {
            float rm = fmaxf(fmaxf(s[i][0], s[i][1]), fmaxf(s[i][2], s[i][3]));
            rm = fmaxf(rm, __shfl_xor_sync(0xffffffffu, rm, 1));
            rm = fmaxf(rm, __shfl_xor_sync(0xffffffffu, rm, 2));
            rm = fmaxf(rm, __shfl_xor_sync(0xffffffffu, rm, 4));
            rm = fmaxf(rm, __shfl_xor_sync(0xffffffffu, rm, 8));
            const float mn = fmaxf(m[i], rm);
            const float alpha = __expf(m[i] - mn);
            m[i] = mn;
            float rs = 0.f;
            #pragma unroll
            for (int j = 0; j < 4; j++) {
                p[i][j] = __expf(s[i][j] - mn);
                rs += p[i][j];
            }
            rs += __shfl_xor_sync(0xffffffffu, rs, 1);
            rs += __shfl_xor_sync(0xffffffffu, rs, 2);
            rs += __shfl_xor_sync(0xffffffffu, rs, 4);
            rs += __shfl_xor_sync(0xffffffffu, rs, 8);
            l[i] = l[i]*alpha + rs;
            #pragma unroll
            for (int j = 0; j < 4; j++) o[i][j] *= alpha;
        }

        __syncthreads();
        #pragma unroll
        for (int i = 0; i < 4; i++)
            #pragma unroll
            for (int j = 0; j < 4; j++)
                Ks[(tx*4 + j)*65 + ty*4 + i] = p[i][j];
        __syncthreads();

        #pragma unroll 16
        for (int c = 0; c < 64; c++) {
            float pv[4], vv[4];
            #pragma unroll
            for (int i = 0; i < 4; i++) pv[i] = Ks[c*65 + ty*4 + i];
            #pragma unroll
            for (int j = 0; j < 4; j++) vv[j] = Vs[c*64 + tx*4 + j];
            #pragma unroll
            for (int i = 0; i < 4; i++)
                #pragma unroll
                for (int j = 0; j < 4; j++)
                    o[i][j] += pv[i]*vv[j];
        }
    }

    const int b = bh >> 4, h = bh & 15;
    #pragma unroll
    for (int i = 0; i < 4; i++) {
        const int r = qt*64 + ty*4 + i;
        const float inv = 1.0f / l[i];
        float4 v;
        v.x = o[i][0]*inv; v.y = o[i][1]*inv; v.z = o[i][2]*inv; v.w = o[i][3]*inv;
        *(float4*)&ctx[((size_t)b*S_ + r)*D_ + h*DK_ + tx*4] = v;
    }
}

// ---------------------------------------------------------------------------
extern "C" void kernel_launch(void* const* d_in, const int* in_sizes, int n_in,
                              void* d_out, int out_size)
{
    const float* q   = (const float*)d_in[0];
    const float* k   = (const float*)d_in[1];
    const float* v   = (const float*)d_in[2];
    // d_in[3] = mask (causal tril, applied analytically)
    const float* w_q = (const float*)d_in[4];
    const float* b_q = (const float*)d_in[5];
    const float* w_k = (const float*)d_in[6];
    const float* b_k = (const float*)d_in[7];
    const float* w_v = (const float*)d_in[8];
    const float* b_v = (const float*)d_in[9];
    const float* w_o = (const float*)d_in[10];
    const float* b_o = (const float*)d_in[11];
    float* out = (float*)d_out;

    float *Qh, *Kh, *Vh, *ctx;
    cudaGetSymbolAddress((void**)&Qh,  g_Qh);
    cudaGetSymbolAddress((void**)&Kh,  g_Kh);
    cudaGetSymbolAddress((void**)&Vh,  g_Vh);
    cudaGetSymbolAddress((void**)&ctx, g_ctx);

    cudaFuncSetAttribute(gemm_mma_kernel<true>,
                         cudaFuncAttributeMaxDynamicSharedMemorySize, GEMM_SMEM);
    cudaFuncSetAttribute(gemm_mma_kernel<false>,
                         cudaFuncAttributeMaxDynamicSharedMemorySize, GEMM_SMEM);

    const int attn_smem = (2*64*65 + 64*64) * sizeof(float);
    cudaFuncSetAttribute(attn_kernel,
                         cudaFuncAttributeMaxDynamicSharedMemorySize, attn_smem);

    const dim3 gemm_grid(D_/128, N_/128);   // (8, 32)
    gemm_mma_kernel<true ><<<gemm_grid, 256, GEMM_SMEM>>>(q, w_q, b_q, Qh);
    gemm_mma_kernel<true ><<<gemm_grid, 256, GEMM_SMEM>>>(k, w_k, b_k, Kh);
    gemm_mma_kernel<true ><<<gemm_grid, 256, GEMM_SMEM>>>(v, w_v, b_v, Vh);

    attn_kernel<<<dim3(S_/64, B_*H_), 256, attn_smem>>>(ctx);

    gemm_mma_kernel<false><<<gemm_grid, 256, GEMM_SMEM>>>(ctx, w_o, b_o, out);
}

// round 6
// speedup vs baseline: 2.4404x; 1.6552x over previous
#include <cuda_runtime.h>
#include <cstdint>
#include <math.h>

#define B_  2
#define S_  2048
#define D_  1024
#define H_  16
#define DK_ 64
#define N_  (B_*S_)

// Scratch (device globals — no allocation allowed)
__device__ float g_Qh[N_*D_];   // [B,H,S,DK]
__device__ float g_Kh[N_*D_];
__device__ float g_Vh[N_*D_];
__device__ float g_ctx[N_*D_];  // [B,S,D]

// ============================ helpers ======================================
__device__ __forceinline__ uint32_t f2tf32(float x) {   // round-to-nearest tf32
    uint32_t r;
    asm("cvt.rna.tf32.f32 %0, %1;" : "=r"(r) : "f"(x));
    return r;
}

__device__ __forceinline__ void mma_tf32(float c[4],
                                         uint32_t a0, uint32_t a1, uint32_t a2, uint32_t a3,
                                         uint32_t b0, uint32_t b1) {
    asm volatile(
        "mma.sync.aligned.m16n8k8.row.col.f32.tf32.tf32.f32 "
        "{%0,%1,%2,%3}, {%4,%5,%6,%7}, {%8,%9}, {%0,%1,%2,%3};"
        : "+f"(c[0]), "+f"(c[1]), "+f"(c[2]), "+f"(c[3])
        : "r"(a0), "r"(a1), "r"(a2), "r"(a3), "r"(b0), "r"(b1));
}

// ===========================================================================
// tf32 tensor-core GEMM: Y = X @ W + bias.  (unchanged from round 5)
// ===========================================================================
#define AS_STRIDE 36
#define BS_STRIDE 136
#define AS_FLOATS (128 * AS_STRIDE)
#define BS_FLOATS (32 * BS_STRIDE)
#define GEMM_SMEM ((2*AS_FLOATS + 2*BS_FLOATS) * 4)   // 71680 B

template<bool SPLIT>
__global__ __launch_bounds__(256, 2)
void gemm_mma_kernel(const float* __restrict__ X, const float* __restrict__ W,
                     const float* __restrict__ bias, float* __restrict__ Y)
{
    extern __shared__ float sm[];
    float* Asb[2] = { sm, sm + AS_FLOATS };
    float* Bsb[2] = { sm + 2*AS_FLOATS, sm + 2*AS_FLOATS + BS_FLOATS };

    const int tid  = threadIdx.x;
    const int wid  = tid >> 5, lane = tid & 31;
    const int g    = lane >> 2, t4 = lane & 3;
    const int wm   = wid >> 2, wn = wid & 3;
    const int rowBase = blockIdx.y * 128;
    const int colBase = blockIdx.x * 128;

    float acc[4][4][4];
    #pragma unroll
    for (int mt = 0; mt < 4; mt++)
        #pragma unroll
        for (int nt = 0; nt < 4; nt++)
            #pragma unroll
            for (int r = 0; r < 4; r++) acc[mt][nt][r] = 0.f;

    #pragma unroll
    for (int j = 0; j < 4; j++) {
        const int slot = tid + 256 * j;
        const int row = slot >> 3, f4 = slot & 7;
        const float4 a = *(const float4*)&X[(size_t)(rowBase + row) * D_ + f4 * 4];
        uint4 ta;
        ta.x = f2tf32(a.x); ta.y = f2tf32(a.y); ta.z = f2tf32(a.z); ta.w = f2tf32(a.w);
        *(uint4*)&Asb[0][row * AS_STRIDE + f4 * 4] = ta;
        const int kr = slot >> 5, nq = slot & 31;
        const float4 b = *(const float4*)&W[(size_t)kr * D_ + colBase + nq * 4];
        uint4 tb;
        tb.x = f2tf32(b.x); tb.y = f2tf32(b.y); tb.z = f2tf32(b.z); tb.w = f2tf32(b.w);
        *(uint4*)&Bsb[0][kr * BS_STRIDE + nq * 4] = tb;
    }

    int buf = 0;
    for (int ch = 0; ch < 32; ch++) {
        __syncthreads();

        float4 ar[4], br[4];
        const bool has_next = (ch + 1 < 32);
        if (has_next) {
            #pragma unroll
            for (int j = 0; j < 4; j++) {
                const int slot = tid + 256 * j;
                const int row = slot >> 3, f4 = slot & 7;
                ar[j] = *(const float4*)&X[(size_t)(rowBase + row) * D_ + (ch+1)*32 + f4 * 4];
                const int kr = slot >> 5, nq = slot & 31;
                br[j] = *(const float4*)&W[(size_t)((ch+1)*32 + kr) * D_ + colBase + nq * 4];
            }
        }

        const float* A = Asb[buf];
        const float* Bv = Bsb[buf];
        #pragma unroll
        for (int ks = 0; ks < 4; ks++) {
            const int k0 = ks * 8;
            uint32_t a[4][4];
            #pragma unroll
            for (int mt = 0; mt < 4; mt++) {
                const int m0 = wm * 64 + mt * 16;
                a[mt][0] = __float_as_uint(A[(m0 + g    ) * AS_STRIDE + k0 + t4    ]);
                a[mt][1] = __float_as_uint(A[(m0 + g + 8) * AS_STRIDE + k0 + t4    ]);
                a[mt][2] = __float_as_uint(A[(m0 + g    ) * AS_STRIDE + k0 + t4 + 4]);
                a[mt][3] = __float_as_uint(A[(m0 + g + 8) * AS_STRIDE + k0 + t4 + 4]);
            }
            #pragma unroll
            for (int nt = 0; nt < 4; nt++) {
                const int n0 = wn * 32 + nt * 8;
                const uint32_t b0 = __float_as_uint(Bv[(k0 + t4    ) * BS_STRIDE + n0 + g]);
                const uint32_t b1 = __float_as_uint(Bv[(k0 + t4 + 4) * BS_STRIDE + n0 + g]);
                #pragma unroll
                for (int mt = 0; mt < 4; mt++)
                    mma_tf32(acc[mt][nt], a[mt][0], a[mt][1], a[mt][2], a[mt][3], b0, b1);
            }
        }

        if (has_next) {
            float* An = Asb[buf ^ 1];
            float* Bn = Bsb[buf ^ 1];
            #pragma unroll
            for (int j = 0; j < 4; j++) {
                const int slot = tid + 256 * j;
                const int row = slot >> 3, f4 = slot & 7;
                uint4 ta;
                ta.x = f2tf32(ar[j].x); ta.y = f2tf32(ar[j].y);
                ta.z = f2tf32(ar[j].z); ta.w = f2tf32(ar[j].w);
                *(uint4*)&An[row * AS_STRIDE + f4 * 4] = ta;
                const int kr = slot >> 5, nq = slot & 31;
                uint4 tb;
                tb.x = f2tf32(br[j].x); tb.y = f2tf32(br[j].y);
                tb.z = f2tf32(br[j].z); tb.w = f2tf32(br[j].w);
                *(uint4*)&Bn[kr * BS_STRIDE + nq * 4] = tb;
            }
        }
        buf ^= 1;
    }

    #pragma unroll
    for (int mt = 0; mt < 4; mt++) {
        const int r0 = rowBase + wm * 64 + mt * 16 + g;
        #pragma unroll
        for (int nt = 0; nt < 4; nt++) {
            const int cb = colBase + wn * 32 + nt * 8 + t4 * 2;
            const float2 bb = *(const float2*)&bias[cb];
            float2 v0, v1;
            v0.x = acc[mt][nt][0] + bb.x; v0.y = acc[mt][nt][1] + bb.y;
            v1.x = acc[mt][nt][2] + bb.x; v1.y = acc[mt][nt][3] + bb.y;
            if (SPLIT) {
                const int h = cb >> 6, dk = cb & (DK_-1);
                const int b0i = r0 >> 11, s0 = r0 & (S_-1);
                *(float2*)&Y[(((b0i*H_ + h)*S_) + s0)*DK_ + dk] = v0;
                const int r1 = r0 + 8;
                const int b1i = r1 >> 11, s1 = r1 & (S_-1);
                *(float2*)&Y[(((b1i*H_ + h)*S_) + s1)*DK_ + dk] = v1;
            } else {
                *(float2*)&Y[(size_t)r0 * D_ + cb] = v0;
                *(float2*)&Y[(size_t)(r0 + 8) * D_ + cb] = v1;
            }
        }
    }
}

// ===========================================================================
// Causal flash attention with tf32 mma.sync.
// Br=128 q-rows per CTA, Bc=64 kv per iteration. 256 threads = 8 warps,
// warp w owns rows [16w, 16w+16). Grid: (qt reversed 16, bh 32).
// smem (floats, stride 68 => conflict-free mma frags):
//   Qs[128][68]  tf32 bits      (34816 B)
//   Ks[64][68]   tf32 bits      (17408 B)
//   Vs[64][68]   tf32 bits      (17408 B)
//   Ps[128][68]  tf32 bits, warp-private rows (34816 B)  => total 104448 B
// ===========================================================================
#define ATT_STRIDE 68
#define ATT_SMEM ((128*ATT_STRIDE + 64*ATT_STRIDE + 64*ATT_STRIDE + 128*ATT_STRIDE) * 4)

__global__ __launch_bounds__(256)
void attn_mma_kernel(float* __restrict__ ctx)
{
    extern __shared__ float smf[];
    float* Qs = smf;                              // [128][68]
    float* Ks = smf + 128*ATT_STRIDE;             // [64][68]
    float* Vs = Ks + 64*ATT_STRIDE;               // [64][68]
    float* Ps = Vs + 64*ATT_STRIDE;               // [128][68]

    const int tid  = threadIdx.x;
    const int wid  = tid >> 5, lane = tid & 31;
    const int g    = lane >> 2, t4 = lane & 3;
    const int qt   = (int)gridDim.x - 1 - (int)blockIdx.x;   // heavy tiles first
    const int bh   = blockIdx.y;
    const int m0   = wid * 16;

    const float* Qg = g_Qh + (size_t)bh * (S_*DK_) + qt * 128 * DK_;
    const float* Kg = g_Kh + (size_t)bh * (S_*DK_);
    const float* Vg = g_Vh + (size_t)bh * (S_*DK_);

    // ---- load Q tile (128x64), convert tf32 ----
    #pragma unroll
    for (int j = 0; j < 8; j++) {
        const int slot = tid + 256 * j;            // 0..2047
        const int row = slot >> 4, cq = (slot & 15) * 4;
        const float4 v = *(const float4*)&Qg[row * DK_ + cq];
        uint4 t;
        t.x = f2tf32(v.x); t.y = f2tf32(v.y); t.z = f2tf32(v.z); t.w = f2tf32(v.w);
        *(uint4*)&Qs[row * ATT_STRIDE + cq] = t;
    }
    // ---- prologue: K/V tile 0 ----
    #pragma unroll
    for (int j = 0; j < 4; j++) {
        const int slot = tid + 256 * j;            // 0..1023
        const int row = slot >> 4, cq = (slot & 15) * 4;
        const float4 kv = *(const float4*)&Kg[row * DK_ + cq];
        uint4 tk;
        tk.x = f2tf32(kv.x); tk.y = f2tf32(kv.y); tk.z = f2tf32(kv.z); tk.w = f2tf32(kv.w);
        *(uint4*)&Ks[row * ATT_STRIDE + cq] = tk;
        const float4 vv = *(const float4*)&Vg[row * DK_ + cq];
        uint4 tv;
        tv.x = f2tf32(vv.x); tv.y = f2tf32(vv.y); tv.z = f2tf32(vv.z); tv.w = f2tf32(vv.w);
        *(uint4*)&Vs[row * ATT_STRIDE + cq] = tv;
    }

    float m[2] = { -1e30f, -1e30f };
    float l[2] = { 0.f, 0.f };
    float o[8][4];
    #pragma unroll
    for (int nt = 0; nt < 8; nt++)
        #pragma unroll
        for (int r = 0; r < 4; r++) o[nt][r] = 0.f;

    const int nk = 2 * qt + 2;
    const int rowg0 = qt * 128 + m0 + g;           // global row for g-half

    for (int kt = 0; kt < nk; kt++) {
        __syncthreads();

        // prefetch next K/V tile into registers
        float4 kr[4], vr[4];
        const bool has_next = (kt + 1 < nk);
        if (has_next) {
            const int base = (kt + 1) * 64;
            #pragma unroll
            for (int j = 0; j < 4; j++) {
                const int slot = tid + 256 * j;
                const int row = slot >> 4, cq = (slot & 15) * 4;
                kr[j] = *(const float4*)&Kg[(base + row) * DK_ + cq];
                vr[j] = *(const float4*)&Vg[(base + row) * DK_ + cq];
            }
        }

        // ---- S = Q K^T (warp rows m0..m0+15, all 64 kv cols) ----
        float sc[8][4];
        #pragma unroll
        for (int nt = 0; nt < 8; nt++)
            #pragma unroll
            for (int r = 0; r < 4; r++) sc[nt][r] = 0.f;

        #pragma unroll
        for (int ks = 0; ks < 8; ks++) {
            const int k0 = ks * 8;
            const uint32_t a0 = __float_as_uint(Qs[(m0 + g    ) * ATT_STRIDE + k0 + t4    ]);
            const uint32_t a1 = __float_as_uint(Qs[(m0 + g + 8) * ATT_STRIDE + k0 + t4    ]);
            const uint32_t a2 = __float_as_uint(Qs[(m0 + g    ) * ATT_STRIDE + k0 + t4 + 4]);
            const uint32_t a3 = __float_as_uint(Qs[(m0 + g + 8) * ATT_STRIDE + k0 + t4 + 4]);
            #pragma unroll
            for (int nt = 0; nt < 8; nt++) {
                const uint32_t b0 = __float_as_uint(Ks[(nt*8 + g) * ATT_STRIDE + k0 + t4    ]);
                const uint32_t b1 = __float_as_uint(Ks[(nt*8 + g) * ATT_STRIDE + k0 + t4 + 4]);
                mma_tf32(sc[nt], a0, a1, a2, a3, b0, b1);
            }
        }

        // ---- scale + causal mask (only partial tiles: kt >= 2*qt) ----
        const bool need_mask = (kt >= 2 * qt);
        const int colBase = kt * 64;
        #pragma unroll
        for (int nt = 0; nt < 8; nt++) {
            #pragma unroll
            for (int r = 0; r < 4; r++) sc[nt][r] *= 0.125f;
            if (need_mask) {
                const int c0 = colBase + nt*8 + 2*t4;
                if (c0     > rowg0    ) sc[nt][0] = -1e30f;
                if (c0 + 1 > rowg0    ) sc[nt][1] = -1e30f;
                if (c0     > rowg0 + 8) sc[nt][2] = -1e30f;
                if (c0 + 1 > rowg0 + 8) sc[nt][3] = -1e30f;
            }
        }

        // ---- online softmax: rows g (sc[.][0,1]) and g+8 (sc[.][2,3]) ----
        #pragma unroll
        for (int r = 0; r < 2; r++) {
            float rm = -1e30f;
            #pragma unroll
            for (int nt = 0; nt < 8; nt++)
                rm = fmaxf(rm, fmaxf(sc[nt][2*r], sc[nt][2*r+1]));
            rm = fmaxf(rm, __shfl_xor_sync(0xffffffffu, rm, 1));
            rm = fmaxf(rm, __shfl_xor_sync(0xffffffffu, rm, 2));
            const float mn = fmaxf(m[r], rm);
            const float alpha = __expf(m[r] - mn);
            m[r] = mn;
            float rs = 0.f;
            #pragma unroll
            for (int nt = 0; nt < 8; nt++) {
                const float p0 = __expf(sc[nt][2*r  ] - mn);
                const float p1 = __expf(sc[nt][2*r+1] - mn);
                sc[nt][2*r] = p0; sc[nt][2*r+1] = p1;
                rs += p0 + p1;
            }
            rs += __shfl_xor_sync(0xffffffffu, rs, 1);
            rs += __shfl_xor_sync(0xffffffffu, rs, 2);
            l[r] = l[r] * alpha + rs;
            #pragma unroll
            for (int nt = 0; nt < 8; nt++) {
                o[nt][2*r] *= alpha; o[nt][2*r+1] *= alpha;
            }
        }

        // ---- P -> Ps (warp-private rows; tf32 bits) ----
        __syncwarp();   // prior PV reads of Ps complete
        #pragma unroll
        for (int nt = 0; nt < 8; nt++) {
            uint2 w0, w1;
            w0.x = f2tf32(sc[nt][0]); w0.y = f2tf32(sc[nt][1]);
            w1.x = f2tf32(sc[nt][2]); w1.y = f2tf32(sc[nt][3]);
            *(uint2*)&Ps[(m0 + g    ) * ATT_STRIDE + nt*8 + 2*t4] = w0;
            *(uint2*)&Ps[(m0 + g + 8) * ATT_STRIDE + nt*8 + 2*t4] = w1;
        }
        __syncwarp();

        // ---- O += P V ----
        #pragma unroll
        for (int ks = 0; ks < 8; ks++) {
            const int k0 = ks * 8;
            const uint32_t a0 = __float_as_uint(Ps[(m0 + g    ) * ATT_STRIDE + k0 + t4    ]);
            const uint32_t a1 = __float_as_uint(Ps[(m0 + g + 8) * ATT_STRIDE + k0 + t4    ]);
            const uint32_t a2 = __float_as_uint(Ps[(m0 + g    ) * ATT_STRIDE + k0 + t4 + 4]);
            const uint32_t a3 = __float_as_uint(Ps[(m0 + g + 8) * ATT_STRIDE + k0 + t4 + 4]);
            #pragma unroll
            for (int nt = 0; nt < 8; nt++) {
                const uint32_t b0 = __float_as_uint(Vs[(k0 + t4    ) * ATT_STRIDE + nt*8 + g]);
                const uint32_t b1 = __float_as_uint(Vs[(k0 + t4 + 4) * ATT_STRIDE + nt*8 + g]);
                mma_tf32(o[nt], a0, a1, a2, a3, b0, b1);
            }
        }

        __syncthreads();   // all warps done with Ks/Vs before overwrite

        if (has_next) {
            #pragma unroll
            for (int j = 0; j < 4; j++) {
                const int slot = tid + 256 * j;
                const int row = slot >> 4, cq = (slot & 15) * 4;
                uint4 tk;
                tk.x = f2tf32(kr[j].x); tk.y = f2tf32(kr[j].y);
                tk.z = f2tf32(kr[j].z); tk.w = f2tf32(kr[j].w);
                *(uint4*)&Ks[row * ATT_STRIDE + cq] = tk;
                uint4 tv;
                tv.x = f2tf32(vr[j].x); tv.y = f2tf32(vr[j].y);
                tv.z = f2tf32(vr[j].z); tv.w = f2tf32(vr[j].w);
                *(uint4*)&Vs[row * ATT_STRIDE + cq] = tv;
            }
        }
    }

    // ---- epilogue: normalize, store ctx [B,S,D] ----
    const int b = bh >> 4, h = bh & 15;
    #pragma unroll
    for (int r = 0; r < 2; r++) {
        const float inv = 1.0f / l[r];
        const int srow = qt*128 + m0 + g + (r ? 8 : 0);
        float* dst = &ctx[((size_t)b * S_ + srow) * D_ + h * DK_];
        #pragma unroll
        for (int nt = 0; nt < 8; nt++) {
            float2 v;
            v.x = o[nt][2*r  ] * inv;
            v.y = o[nt][2*r+1] * inv;
            *(float2*)&dst[nt*8 + 2*t4] = v;
        }
    }
}

// ---------------------------------------------------------------------------
extern "C" void kernel_launch(void* const* d_in, const int* in_sizes, int n_in,
                              void* d_out, int out_size)
{
    const float* q   = (const float*)d_in[0];
    const float* k   = (const float*)d_in[1];
    const float* v   = (const float*)d_in[2];
    // d_in[3] = mask (causal tril, applied analytically)
    const float* w_q = (const float*)d_in[4];
    const float* b_q = (const float*)d_in[5];
    const float* w_k = (const float*)d_in[6];
    const float* b_k = (const float*)d_in[7];
    const float* w_v = (const float*)d_in[8];
    const float* b_v = (const float*)d_in[9];
    const float* w_o = (const float*)d_in[10];
    const float* b_o = (const float*)d_in[11];
    float* out = (float*)d_out;

    float *Qh, *Kh, *Vh, *ctx;
    cudaGetSymbolAddress((void**)&Qh,  g_Qh);
    cudaGetSymbolAddress((void**)&Kh,  g_Kh);
    cudaGetSymbolAddress((void**)&Vh,  g_Vh);
    cudaGetSymbolAddress((void**)&ctx, g_ctx);

    cudaFuncSetAttribute(gemm_mma_kernel<true>,
                         cudaFuncAttributeMaxDynamicSharedMemorySize, GEMM_SMEM);
    cudaFuncSetAttribute(gemm_mma_kernel<false>,
                         cudaFuncAttributeMaxDynamicSharedMemorySize, GEMM_SMEM);
    cudaFuncSetAttribute(attn_mma_kernel,
                         cudaFuncAttributeMaxDynamicSharedMemorySize, ATT_SMEM);

    const dim3 gemm_grid(D_/128, N_/128);   // (8, 32)
    gemm_mma_kernel<true ><<<gemm_grid, 256, GEMM_SMEM>>>(q, w_q, b_q, Qh);
    gemm_mma_kernel<true ><<<gemm_grid, 256, GEMM_SMEM>>>(k, w_k, b_k, Kh);
    gemm_mma_kernel<true ><<<gemm_grid, 256, GEMM_SMEM>>>(v, w_v, b_v, Vh);

    attn_mma_kernel<<<dim3(S_/128, B_*H_), 256, ATT_SMEM>>>(ctx);

    gemm_mma_kernel<false><<<gemm_grid, 256, GEMM_SMEM>>>(ctx, w_o, b_o, out);
}

// round 7
// speedup vs baseline: 3.1338x; 1.2841x over previous
#include <cuda_runtime.h>
#include <cstdint>
#include <math.h>

#define B_  2
#define S_  2048
#define D_  1024
#define H_  16
#define DK_ 64
#define N_  (B_*S_)

// Scratch (device globals — no allocation allowed). All tf32-bit payloads.
__device__ uint32_t g_qt[N_*D_];    // tf32(q)
__device__ uint32_t g_kt[N_*D_];
__device__ uint32_t g_vt[N_*D_];
__device__ uint32_t g_wqt[D_*D_];   // tf32(w_q) ...
__device__ uint32_t g_wkt[D_*D_];
__device__ uint32_t g_wvt[D_*D_];
__device__ uint32_t g_wot[D_*D_];
__device__ uint32_t g_Qh[N_*D_];    // [B,H,S,DK] tf32
__device__ uint32_t g_Kh[N_*D_];
__device__ uint32_t g_Vh[N_*D_];
__device__ uint32_t g_ctx[N_*D_];   // [B,S,D] tf32

// ============================ helpers ======================================
__device__ __forceinline__ uint32_t f2tf32(float x) {   // round-to-nearest tf32
    uint32_t r;
    asm("cvt.rna.tf32.f32 %0, %1;" : "=r"(r) : "f"(x));
    return r;
}
__device__ __forceinline__ uint32_t smem_u32(const void* p) {
    uint32_t a;
    asm("{ .reg .u64 t; cvta.to.shared.u64 t, %1; cvt.u32.u64 %0, t; }"
        : "=r"(a) : "l"(p));
    return a;
}
__device__ __forceinline__ void cp16(uint32_t sdst, const void* gsrc) {
    asm volatile("cp.async.cg.shared.global [%0], [%1], 16;"
                 :: "r"(sdst), "l"(gsrc) : "memory");
}
#define CP_COMMIT() asm volatile("cp.async.commit_group;" ::: "memory")
#define CP_WAIT1()  asm volatile("cp.async.wait_group 1;" ::: "memory")

__device__ __forceinline__ void mma_tf32(float c[4],
                                         uint32_t a0, uint32_t a1, uint32_t a2, uint32_t a3,
                                         uint32_t b0, uint32_t b1) {
    asm volatile(
        "mma.sync.aligned.m16n8k8.row.col.f32.tf32.tf32.f32 "
        "{%0,%1,%2,%3}, {%4,%5,%6,%7}, {%8,%9}, {%0,%1,%2,%3};"
        : "+f"(c[0]), "+f"(c[1]), "+f"(c[2]), "+f"(c[3])
        : "r"(a0), "r"(a1), "r"(a2), "r"(a3), "r"(b0), "r"(b1));
}

// ===========================================================================
// fp32 -> tf32 bit conversion pass
// ===========================================================================
__global__ __launch_bounds__(256) void cvt_tf32_kernel(
    const float* __restrict__ in, uint32_t* __restrict__ out)
{
    const int i = (blockIdx.x * 256 + threadIdx.x) * 4;
    const float4 v = *(const float4*)&in[i];
    uint4 t;
    t.x = f2tf32(v.x); t.y = f2tf32(v.y); t.z = f2tf32(v.z); t.w = f2tf32(v.w);
    *(uint4*)&out[i] = t;
}

// ===========================================================================
// tf32 GEMM with cp.async 3-stage pipeline: Y = A @ Bm + bias.
// A:[4096,1024] tf32 bits, Bm:[1024,1024] tf32 bits, both row-major.
// CTA 128x128, K-chunk 32, 8 warps (2m x 4n), warp tile 64x32.
// SPLIT: Y = uint32 tf32 bits in [B,H,S,DK]; else Y = float [.,1024].
// ===========================================================================
#define AS_STRIDE 36
#define BS_STRIDE 136
#define AST_FLOATS (128 * AS_STRIDE)     // 4608
#define BST_FLOATS (32 * BS_STRIDE)      // 4352
#define STG_FLOATS (AST_FLOATS + BST_FLOATS)
#define GEMM_SMEM (3 * STG_FLOATS * 4)   // 107520 B

template<bool SPLIT>
__global__ __launch_bounds__(256, 2)
void gemm_cp_kernel(const uint32_t* __restrict__ A_, const uint32_t* __restrict__ Bm,
                    const float* __restrict__ bias, void* __restrict__ Yv)
{
    extern __shared__ uint32_t smu[];
    const uint32_t smem_base = smem_u32(smu);

    const int tid  = threadIdx.x;
    const int wid  = tid >> 5, lane = tid & 31;
    const int g    = lane >> 2, t4 = lane & 3;
    const int wm   = wid >> 2, wn = wid & 3;
    const int rowBase = blockIdx.y * 128;
    const int colBase = blockIdx.x * 128;

    // per-thread copy slots (4 A float4s + 4 B float4s per chunk)
    const int ar_row[1] = {0};  (void)ar_row;

    auto issue = [&](int ch, int stg) {
        const uint32_t abase = smem_base + (uint32_t)stg * (STG_FLOATS * 4);
        const uint32_t bbase = abase + AST_FLOATS * 4;
        #pragma unroll
        for (int j = 0; j < 4; j++) {
            const int slot = tid + 256 * j;
            const int row = slot >> 3, f4 = slot & 7;
            cp16(abase + (row * AS_STRIDE + f4 * 4) * 4,
                 A_ + (size_t)(rowBase + row) * D_ + ch * 32 + f4 * 4);
            const int kr = slot >> 5, nq = slot & 31;
            cp16(bbase + (kr * BS_STRIDE + nq * 4) * 4,
                 Bm + (size_t)(ch * 32 + kr) * D_ + colBase + nq * 4);
        }
        CP_COMMIT();
    };

    float acc[4][4][4];
    #pragma unroll
    for (int mt = 0; mt < 4; mt++)
        #pragma unroll
        for (int nt = 0; nt < 4; nt++)
            #pragma unroll
            for (int r = 0; r < 4; r++) acc[mt][nt][r] = 0.f;

    issue(0, 0);
    issue(1, 1);

    for (int ch = 0; ch < 32; ch++) {
        CP_WAIT1();
        __syncthreads();

        if (ch + 2 < 32) issue(ch + 2, (ch + 2) % 3);

        const uint32_t* A  = smu + (ch % 3) * STG_FLOATS;
        const uint32_t* Bv = A + AST_FLOATS;

        #pragma unroll
        for (int ks = 0; ks < 4; ks++) {
            const int k0 = ks * 8;
            uint32_t a[4][4];
            #pragma unroll
            for (int mt = 0; mt < 4; mt++) {
                const int m0 = wm * 64 + mt * 16;
                a[mt][0] = A[(m0 + g    ) * AS_STRIDE + k0 + t4    ];
                a[mt][1] = A[(m0 + g + 8) * AS_STRIDE + k0 + t4    ];
                a[mt][2] = A[(m0 + g    ) * AS_STRIDE + k0 + t4 + 4];
                a[mt][3] = A[(m0 + g + 8) * AS_STRIDE + k0 + t4 + 4];
            }
            #pragma unroll
            for (int nt = 0; nt < 4; nt++) {
                const int n0 = wn * 32 + nt * 8;
                const uint32_t b0 = Bv[(k0 + t4    ) * BS_STRIDE + n0 + g];
                const uint32_t b1 = Bv[(k0 + t4 + 4) * BS_STRIDE + n0 + g];
                #pragma unroll
                for (int mt = 0; mt < 4; mt++)
                    mma_tf32(acc[mt][nt], a[mt][0], a[mt][1], a[mt][2], a[mt][3], b0, b1);
            }
        }
        __syncthreads();
    }

    // ---- epilogue ----
    #pragma unroll
    for (int mt = 0; mt < 4; mt++) {
        const int r0 = rowBase + wm * 64 + mt * 16 + g;
        #pragma unroll
        for (int nt = 0; nt < 4; nt++) {
            const int cb = colBase + wn * 32 + nt * 8 + t4 * 2;
            const float2 bb = *(const float2*)&bias[cb];
            float2 v0, v1;
            v0.x = acc[mt][nt][0] + bb.x; v0.y = acc[mt][nt][1] + bb.y;
            v1.x = acc[mt][nt][2] + bb.x; v1.y = acc[mt][nt][3] + bb.y;
            if (SPLIT) {
                uint32_t* Y = (uint32_t*)Yv;
                const int h = cb >> 6, dk = cb & (DK_-1);
                const int b0i = r0 >> 11, s0 = r0 & (S_-1);
                uint2 u0; u0.x = f2tf32(v0.x); u0.y = f2tf32(v0.y);
                *(uint2*)&Y[(((b0i*H_ + h)*S_) + s0)*DK_ + dk] = u0;
                const int r1 = r0 + 8;
                const int b1i = r1 >> 11, s1 = r1 & (S_-1);
                uint2 u1; u1.x = f2tf32(v1.x); u1.y = f2tf32(v1.y);
                *(uint2*)&Y[(((b1i*H_ + h)*S_) + s1)*DK_ + dk] = u1;
            } else {
                float* Y = (float*)Yv;
                *(float2*)&Y[(size_t)r0 * D_ + cb] = v0;
                *(float2*)&Y[(size_t)(r0 + 8) * D_ + cb] = v1;
            }
        }
    }
}

// ===========================================================================
// Causal flash attention, tf32 mma.sync. Inputs/outputs are tf32 bits.
// Br=128, Bc=64, 8 warps; warp w owns rows [16w,16w+16).
// ===========================================================================
#define ATT_STRIDE 68
#define ATT_SMEM ((128*ATT_STRIDE + 64*ATT_STRIDE + 64*ATT_STRIDE + 128*ATT_STRIDE) * 4)

__global__ __launch_bounds__(256)
void attn_mma_kernel(uint32_t* __restrict__ ctx)
{
    extern __shared__ uint32_t smw[];
    uint32_t* Qs = smw;                           // [128][68]
    uint32_t* Ks = smw + 128*ATT_STRIDE;          // [64][68]
    uint32_t* Vs = Ks + 64*ATT_STRIDE;            // [64][68]
    uint32_t* Ps = Vs + 64*ATT_STRIDE;            // [128][68]

    const int tid  = threadIdx.x;
    const int wid  = tid >> 5, lane = tid & 31;
    const int g    = lane >> 2, t4 = lane & 3;
    const int qt   = (int)gridDim.x - 1 - (int)blockIdx.x;   // heavy tiles first
    const int bh   = blockIdx.y;
    const int m0   = wid * 16;

    const uint32_t* Qg = g_Qh + (size_t)bh * (S_*DK_) + qt * 128 * DK_;
    const uint32_t* Kg = g_Kh + (size_t)bh * (S_*DK_);
    const uint32_t* Vg = g_Vh + (size_t)bh * (S_*DK_);

    // ---- load Q tile (tf32 bits, plain copy) ----
    #pragma unroll
    for (int j = 0; j < 8; j++) {
        const int slot = tid + 256 * j;
        const int row = slot >> 4, cq = (slot & 15) * 4;
        *(uint4*)&Qs[row * ATT_STRIDE + cq] = *(const uint4*)&Qg[row * DK_ + cq];
    }
    // ---- prologue: K/V tile 0 ----
    #pragma unroll
    for (int j = 0; j < 4; j++) {
        const int slot = tid + 256 * j;
        const int row = slot >> 4, cq = (slot & 15) * 4;
        *(uint4*)&Ks[row * ATT_STRIDE + cq] = *(const uint4*)&Kg[row * DK_ + cq];
        *(uint4*)&Vs[row * ATT_STRIDE + cq] = *(const uint4*)&Vg[row * DK_ + cq];
    }

    float m[2] = { -1e30f, -1e30f };
    float l[2] = { 0.f, 0.f };
    float o[8][4];
    #pragma unroll
    for (int nt = 0; nt < 8; nt++)
        #pragma unroll
        for (int r = 0; r < 4; r++) o[nt][r] = 0.f;

    const int nk = 2 * qt + 2;
    const int rowg0 = qt * 128 + m0 + g;

    for (int kt = 0; kt < nk; kt++) {
        __syncthreads();

        // prefetch next K/V tile into registers
        uint4 kr[4], vr[4];
        const bool has_next = (kt + 1 < nk);
        if (has_next) {
            const int base = (kt + 1) * 64;
            #pragma unroll
            for (int j = 0; j < 4; j++) {
                const int slot = tid + 256 * j;
                const int row = slot >> 4, cq = (slot & 15) * 4;
                kr[j] = *(const uint4*)&Kg[(base + row) * DK_ + cq];
                vr[j] = *(const uint4*)&Vg[(base + row) * DK_ + cq];
            }
        }

        // ---- S = Q K^T ----
        float sc[8][4];
        #pragma unroll
        for (int nt = 0; nt < 8; nt++)
            #pragma unroll
            for (int r = 0; r < 4; r++) sc[nt][r] = 0.f;

        #pragma unroll
        for (int ks = 0; ks < 8; ks++) {
            const int k0 = ks * 8;
            const uint32_t a0 = Qs[(m0 + g    ) * ATT_STRIDE + k0 + t4    ];
            const uint32_t a1 = Qs[(m0 + g + 8) * ATT_STRIDE + k0 + t4    ];
            const uint32_t a2 = Qs[(m0 + g    ) * ATT_STRIDE + k0 + t4 + 4];
            const uint32_t a3 = Qs[(m0 + g + 8) * ATT_STRIDE + k0 + t4 + 4];
            #pragma unroll
            for (int nt = 0; nt < 8; nt++) {
                const uint32_t b0 = Ks[(nt*8 + g) * ATT_STRIDE + k0 + t4    ];
                const uint32_t b1 = Ks[(nt*8 + g) * ATT_STRIDE + k0 + t4 + 4];
                mma_tf32(sc[nt], a0, a1, a2, a3, b0, b1);
            }
        }

        // ---- scale + causal mask ----
        const bool need_mask = (kt >= 2 * qt);
        const int colBase = kt * 64;
        #pragma unroll
        for (int nt = 0; nt < 8; nt++) {
            #pragma unroll
            for (int r = 0; r < 4; r++) sc[nt][r] *= 0.125f;
            if (need_mask) {
                const int c0 = colBase + nt*8 + 2*t4;
                if (c0     > rowg0    ) sc[nt][0] = -1e30f;
                if (c0 + 1 > rowg0    ) sc[nt][1] = -1e30f;
                if (c0     > rowg0 + 8) sc[nt][2] = -1e30f;
                if (c0 + 1 > rowg0 + 8) sc[nt][3] = -1e30f;
            }
        }

        // ---- online softmax ----
        #pragma unroll
        for (int r = 0; r < 2; r++) {
            float rm = -1e30f;
            #pragma unroll
            for (int nt = 0; nt < 8; nt++)
                rm = fmaxf(rm, fmaxf(sc[nt][2*r], sc[nt][2*r+1]));
            rm = fmaxf(rm, __shfl_xor_sync(0xffffffffu, rm, 1));
            rm = fmaxf(rm, __shfl_xor_sync(0xffffffffu, rm, 2));
            const float mn = fmaxf(m[r], rm);
            const float alpha = __expf(m[r] - mn);
            m[r] = mn;
            float rs = 0.f;
            #pragma unroll
            for (int nt = 0; nt < 8; nt++) {
                const float p0 = __expf(sc[nt][2*r  ] - mn);
                const float p1 = __expf(sc[nt][2*r+1] - mn);
                sc[nt][2*r] = p0; sc[nt][2*r+1] = p1;
                rs += p0 + p1;
            }
            rs += __shfl_xor_sync(0xffffffffu, rs, 1);
            rs += __shfl_xor_sync(0xffffffffu, rs, 2);
            l[r] = l[r] * alpha + rs;
            #pragma unroll
            for (int nt = 0; nt < 8; nt++) {
                o[nt][2*r] *= alpha; o[nt][2*r+1] *= alpha;
            }
        }

        // ---- P -> Ps (warp-private rows; tf32 bits) ----
        __syncwarp();
        #pragma unroll
        for (int nt = 0; nt < 8; nt++) {
            uint2 w0, w1;
            w0.x = f2tf32(sc[nt][0]); w0.y = f2tf32(sc[nt][1]);
            w1.x = f2tf32(sc[nt][2]); w1.y = f2tf32(sc[nt][3]);
            *(uint2*)&Ps[(m0 + g    ) * ATT_STRIDE + nt*8 + 2*t4] = w0;
            *(uint2*)&Ps[(m0 + g + 8) * ATT_STRIDE + nt*8 + 2*t4] = w1;
        }
        __syncwarp();

        // ---- O += P V ----
        #pragma unroll
        for (int ks = 0; ks < 8; ks++) {
            const int k0 = ks * 8;
            const uint32_t a0 = Ps[(m0 + g    ) * ATT_STRIDE + k0 + t4    ];
            const uint32_t a1 = Ps[(m0 + g + 8) * ATT_STRIDE + k0 + t4    ];
            const uint32_t a2 = Ps[(m0 + g    ) * ATT_STRIDE + k0 + t4 + 4];
            const uint32_t a3 = Ps[(m0 + g + 8) * ATT_STRIDE + k0 + t4 + 4];
            #pragma unroll
            for (int nt = 0; nt < 8; nt++) {
                const uint32_t b0 = Vs[(k0 + t4    ) * ATT_STRIDE + nt*8 + g];
                const uint32_t b1 = Vs[(k0 + t4 + 4) * ATT_STRIDE + nt*8 + g];
                mma_tf32(o[nt], a0, a1, a2, a3, b0, b1);
            }
        }

        __syncthreads();

        if (has_next) {
            #pragma unroll
            for (int j = 0; j < 4; j++) {
                const int slot = tid + 256 * j;
                const int row = slot >> 4, cq = (slot & 15) * 4;
                *(uint4*)&Ks[row * ATT_STRIDE + cq] = kr[j];
                *(uint4*)&Vs[row * ATT_STRIDE + cq] = vr[j];
            }
        }
    }

    // ---- epilogue: normalize, store ctx as tf32 bits [B,S,D] ----
    const int b = bh >> 4, h = bh & 15;
    #pragma unroll
    for (int r = 0; r < 2; r++) {
        const float inv = 1.0f / l[r];
        const int srow = qt*128 + m0 + g + (r ? 8 : 0);
        uint32_t* dst = &ctx[((size_t)b * S_ + srow) * D_ + h * DK_];
        #pragma unroll
        for (int nt = 0; nt < 8; nt++) {
            uint2 v;
            v.x = f2tf32(o[nt][2*r  ] * inv);
            v.y = f2tf32(o[nt][2*r+1] * inv);
            *(uint2*)&dst[nt*8 + 2*t4] = v;
        }
    }
}

// ---------------------------------------------------------------------------
extern "C" void kernel_launch(void* const* d_in, const int* in_sizes, int n_in,
                              void* d_out, int out_size)
{
    const float* q   = (const float*)d_in[0];
    const float* k   = (const float*)d_in[1];
    const float* v   = (const float*)d_in[2];
    // d_in[3] = mask (causal tril, applied analytically)
    const float* w_q = (const float*)d_in[4];
    const float* b_q = (const float*)d_in[5];
    const float* w_k = (const float*)d_in[6];
    const float* b_k = (const float*)d_in[7];
    const float* w_v = (const float*)d_in[8];
    const float* b_v = (const float*)d_in[9];
    const float* w_o = (const float*)d_in[10];
    const float* b_o = (const float*)d_in[11];
    float* out = (float*)d_out;

    uint32_t *qt, *kt, *vt, *wqt, *wkt, *wvt, *wot, *Qh, *Kh, *Vh, *ctx;
    cudaGetSymbolAddress((void**)&qt,  g_qt);
    cudaGetSymbolAddress((void**)&kt,  g_kt);
    cudaGetSymbolAddress((void**)&vt,  g_vt);
    cudaGetSymbolAddress((void**)&wqt, g_wqt);
    cudaGetSymbolAddress((void**)&wkt, g_wkt);
    cudaGetSymbolAddress((void**)&wvt, g_wvt);
    cudaGetSymbolAddress((void**)&wot, g_wot);
    cudaGetSymbolAddress((void**)&Qh,  g_Qh);
    cudaGetSymbolAddress((void**)&Kh,  g_Kh);
    cudaGetSymbolAddress((void**)&Vh,  g_Vh);
    cudaGetSymbolAddress((void**)&ctx, g_ctx);

    cudaFuncSetAttribute(gemm_cp_kernel<true>,
                         cudaFuncAttributeMaxDynamicSharedMemorySize, GEMM_SMEM);
    cudaFuncSetAttribute(gemm_cp_kernel<false>,
                         cudaFuncAttributeMaxDynamicSharedMemorySize, GEMM_SMEM);
    cudaFuncSetAttribute(attn_mma_kernel,
                         cudaFuncAttributeMaxDynamicSharedMemorySize, ATT_SMEM);

    // pre-convert inputs + weights to tf32 bits
    cvt_tf32_kernel<<<N_*D_/1024, 256>>>(q, qt);
    cvt_tf32_kernel<<<N_*D_/1024, 256>>>(k, kt);
    cvt_tf32_kernel<<<N_*D_/1024, 256>>>(v, vt);
    cvt_tf32_kernel<<<D_*D_/1024, 256>>>(w_q, wqt);
    cvt_tf32_kernel<<<D_*D_/1024, 256>>>(w_k, wkt);
    cvt_tf32_kernel<<<D_*D_/1024, 256>>>(w_v, wvt);
    cvt_tf32_kernel<<<D_*D_/1024, 256>>>(w_o, wot);

    const dim3 gemm_grid(D_/128, N_/128);   // (8, 32)
    gemm_cp_kernel<true ><<<gemm_grid, 256, GEMM_SMEM>>>(qt, wqt, b_q, Qh);
    gemm_cp_kernel<true ><<<gemm_grid, 256, GEMM_SMEM>>>(kt, wkt, b_k, Kh);
    gemm_cp_kernel<true ><<<gemm_grid, 256, GEMM_SMEM>>>(vt, wvt, b_v, Vh);

    attn_mma_kernel<<<dim3(S_/128, B_*H_), 256, ATT_SMEM>>>(ctx);

    gemm_cp_kernel<false><<<gemm_grid, 256, GEMM_SMEM>>>(ctx, wot, b_o, out);
}